// round 6
// baseline (speedup 1.0000x reference)
#include <cuda_runtime.h>

#define NN 50000
#define NE 1000000

typedef unsigned long long u64;

// ---------------------------------------------------------------------------
// packed f32x2 helpers (sm_103a FFMA2 — PTX-only)
// ---------------------------------------------------------------------------
__device__ __forceinline__ u64 ffma2(u64 a, u64 b, u64 c) {
    u64 d; asm("fma.rn.f32x2 %0, %1, %2, %3;" : "=l"(d) : "l"(a), "l"(b), "l"(c));
    return d;
}
__device__ __forceinline__ float hadd2(u64 a) {
    float lo, hi; asm("mov.b64 {%0, %1}, %2;" : "=f"(lo), "=f"(hi) : "l"(a));
    return lo + hi;
}

// Scratch (allocation-free rule: __device__ globals)
__device__ __align__(128) float g_P[NN * 64];   // x_v @ W_av^T
__device__ __align__(128) float g_S[NN * 64];   // unnormalized weighted message sums
__device__ __align__(128) float g_den[NN];      // sum of exp(e) per dst

// NOTE: one row of a 64x64 weight matrix = 64 floats = 16 ulonglong2.

// ---------------------------------------------------------------------------
// K0: P = x_v @ W_av^T ; zero S and den.  ONE NODE PER THREAD.
// Weight LDS is warp-uniform (broadcast, N=1). Packed FMA.
// ---------------------------------------------------------------------------
__global__ void __launch_bounds__(256) node_pre_kernel(
    const float* __restrict__ x_v, const float* __restrict__ W_av)
{
    __shared__ ulonglong2 sW[64][16];   // [row j][k4]  (16 KB)
    int tid = threadIdx.x;
    for (int i = tid; i < 1024; i += 256)
        ((ulonglong2*)sW)[i] = ((const ulonglong2*)W_av)[i];
    __syncthreads();

    int n = blockIdx.x * 256 + tid;
    if (n >= NN) return;

    ulonglong2 xp[16];
    const ulonglong2* xg = (const ulonglong2*)(x_v + (size_t)n * 64);
#pragma unroll
    for (int k = 0; k < 16; k++) xp[k] = xg[k];

    float4* Pn = (float4*)(g_P + (size_t)n * 64);
    float4* Sn = (float4*)(g_S + (size_t)n * 64);
    float4 z4 = make_float4(0.f, 0.f, 0.f, 0.f);
#pragma unroll
    for (int q = 0; q < 16; q++) {
        int j0 = q * 4;
        u64 a0 = 0, a1 = 0, a2 = 0, a3 = 0;
#pragma unroll
        for (int k = 0; k < 16; k++) {
            ulonglong2 x = xp[k];
            ulonglong2 w0 = sW[j0 + 0][k], w1 = sW[j0 + 1][k];
            ulonglong2 w2 = sW[j0 + 2][k], w3 = sW[j0 + 3][k];
            a0 = ffma2(x.x, w0.x, a0); a0 = ffma2(x.y, w0.y, a0);
            a1 = ffma2(x.x, w1.x, a1); a1 = ffma2(x.y, w1.y, a1);
            a2 = ffma2(x.x, w2.x, a2); a2 = ffma2(x.y, w2.y, a2);
            a3 = ffma2(x.x, w3.x, a3); a3 = ffma2(x.y, w3.y, a3);
        }
        Pn[q] = make_float4(hadd2(a0), hadd2(a1), hadd2(a2), hadd2(a3));
        Sn[q] = z4;
    }
    g_den[n] = 0.f;
}

// ---------------------------------------------------------------------------
// K1: edge kernel. One thread per edge, broadcast weights in SMEM, FFMA2.
// ---------------------------------------------------------------------------
__global__ void __launch_bounds__(256) edge_kernel(
    const float* __restrict__ x_a, const int* __restrict__ arc,
    const float* __restrict__ W_va,
    const float* __restrict__ W_att, const float* __restrict__ b_att,
    const float* __restrict__ W_aa, const float* __restrict__ b_aa,
    float* __restrict__ out_a)
{
    __shared__ ulonglong2 sWva[64][16];   // 16 KB
    __shared__ ulonglong2 sWaa[64][16];   // 16 KB
    __shared__ ulonglong2 sAtt[16];
    __shared__ float      sBaa[64];
    __shared__ float      sBatt;

    int tid = threadIdx.x;
    for (int i = tid; i < 1024; i += 256) {
        ((ulonglong2*)sWva)[i] = ((const ulonglong2*)W_va)[i];
        ((ulonglong2*)sWaa)[i] = ((const ulonglong2*)W_aa)[i];
    }
    if (tid < 16) sAtt[tid] = ((const ulonglong2*)W_att)[tid];
    if (tid < 64) sBaa[tid] = b_aa[tid];
    if (tid == 0) sBatt = b_att[0];
    __syncthreads();

    int e = blockIdx.x * 256 + tid;
    if (e >= NE) return;

    ulonglong2 xp[16];
    const ulonglong2* xg = (const ulonglong2*)(x_a + (size_t)e * 64);
#pragma unroll
    for (int k = 0; k < 16; k++) xp[k] = xg[k];

    // attention logit + unnormalized softmax weight (max-shift cancels)
    u64 ea = 0;
#pragma unroll
    for (int k = 0; k < 16; k++) {
        ulonglong2 x = xp[k], wv = sAtt[k];
        ea = ffma2(x.x, wv.x, ea);
        ea = ffma2(x.y, wv.y, ea);
    }
    float w = __expf(hadd2(ea) + sBatt);

    int src = arc[e];
    int dst = arc[NE + e];
    atomicAdd(&g_den[dst], w);

    // weighted message scatter: S[dst] += w * (x_a @ W_va^T)
    float* Sd = g_S + (size_t)dst * 64;
#pragma unroll
    for (int q = 0; q < 16; q++) {
        int j0 = q * 4;
        u64 a0 = 0, a1 = 0, a2 = 0, a3 = 0;
#pragma unroll
        for (int k = 0; k < 16; k++) {
            ulonglong2 x = xp[k];
            ulonglong2 w0 = sWva[j0 + 0][k], w1 = sWva[j0 + 1][k];
            ulonglong2 w2 = sWva[j0 + 2][k], w3 = sWva[j0 + 3][k];
            a0 = ffma2(x.x, w0.x, a0); a0 = ffma2(x.y, w0.y, a0);
            a1 = ffma2(x.x, w1.x, a1); a1 = ffma2(x.y, w1.y, a1);
            a2 = ffma2(x.x, w2.x, a2); a2 = ffma2(x.y, w2.y, a2);
            a3 = ffma2(x.x, w3.x, a3); a3 = ffma2(x.y, w3.y, a3);
        }
        asm volatile("red.global.add.v4.f32 [%0], {%1, %2, %3, %4};"
                     :: "l"(Sd + j0),
                        "f"(hadd2(a0) * w), "f"(hadd2(a1) * w),
                        "f"(hadd2(a2) * w), "f"(hadd2(a3) * w)
                     : "memory");
    }

    // arc update: out_a = x_a @ W_aa^T + b_aa + P[src] + P[dst]
    const float4* Ps = (const float4*)(g_P + (size_t)src * 64);
    const float4* Pd = (const float4*)(g_P + (size_t)dst * 64);
    float4* Oa = (float4*)(out_a + (size_t)e * 64);
#pragma unroll
    for (int q = 0; q < 16; q++) {
        int j0 = q * 4;
        u64 a0 = 0, a1 = 0, a2 = 0, a3 = 0;
#pragma unroll
        for (int k = 0; k < 16; k++) {
            ulonglong2 x = xp[k];
            ulonglong2 w0 = sWaa[j0 + 0][k], w1 = sWaa[j0 + 1][k];
            ulonglong2 w2 = sWaa[j0 + 2][k], w3 = sWaa[j0 + 3][k];
            a0 = ffma2(x.x, w0.x, a0); a0 = ffma2(x.y, w0.y, a0);
            a1 = ffma2(x.x, w1.x, a1); a1 = ffma2(x.y, w1.y, a1);
            a2 = ffma2(x.x, w2.x, a2); a2 = ffma2(x.y, w2.y, a2);
            a3 = ffma2(x.x, w3.x, a3); a3 = ffma2(x.y, w3.y, a3);
        }
        float4 ps = Ps[q], pd = Pd[q];
        float4 o;
        o.x = hadd2(a0) + sBaa[j0 + 0] + ps.x + pd.x;
        o.y = hadd2(a1) + sBaa[j0 + 1] + ps.y + pd.y;
        o.z = hadd2(a2) + sBaa[j0 + 2] + ps.z + pd.z;
        o.w = hadd2(a3) + sBaa[j0 + 3] + ps.w + pd.w;
        Oa[q] = o;
    }
}

// ---------------------------------------------------------------------------
// K2: h_v = x_v @ W_vv^T + b_vv + S/den.  ONE NODE PER THREAD.
// ---------------------------------------------------------------------------
__global__ void __launch_bounds__(256) node_post_kernel(
    const float* __restrict__ x_v, const float* __restrict__ W_vv,
    const float* __restrict__ b_vv, float* __restrict__ out_v)
{
    __shared__ ulonglong2 sW[64][16];
    __shared__ float sb[64];
    int tid = threadIdx.x;
    for (int i = tid; i < 1024; i += 256)
        ((ulonglong2*)sW)[i] = ((const ulonglong2*)W_vv)[i];
    if (tid < 64) sb[tid] = b_vv[tid];
    __syncthreads();

    int n = blockIdx.x * 256 + tid;
    if (n >= NN) return;

    ulonglong2 xp[16];
    const ulonglong2* xg = (const ulonglong2*)(x_v + (size_t)n * 64);
#pragma unroll
    for (int k = 0; k < 16; k++) xp[k] = xg[k];

    float den = g_den[n];
    float inv = (den > 0.f) ? (1.f / den) : 0.f;
    const float4* Sn = (const float4*)(g_S + (size_t)n * 64);
    float4* Ov = (float4*)(out_v + (size_t)n * 64);

#pragma unroll
    for (int q = 0; q < 16; q++) {
        int j0 = q * 4;
        u64 a0 = 0, a1 = 0, a2 = 0, a3 = 0;
#pragma unroll
        for (int k = 0; k < 16; k++) {
            ulonglong2 x = xp[k];
            ulonglong2 w0 = sW[j0 + 0][k], w1 = sW[j0 + 1][k];
            ulonglong2 w2 = sW[j0 + 2][k], w3 = sW[j0 + 3][k];
            a0 = ffma2(x.x, w0.x, a0); a0 = ffma2(x.y, w0.y, a0);
            a1 = ffma2(x.x, w1.x, a1); a1 = ffma2(x.y, w1.y, a1);
            a2 = ffma2(x.x, w2.x, a2); a2 = ffma2(x.y, w2.y, a2);
            a3 = ffma2(x.x, w3.x, a3); a3 = ffma2(x.y, w3.y, a3);
        }
        float4 s = Sn[q];
        float4 o;
        o.x = hadd2(a0) + sb[j0 + 0] + s.x * inv;
        o.y = hadd2(a1) + sb[j0 + 1] + s.y * inv;
        o.z = hadd2(a2) + sb[j0 + 2] + s.z * inv;
        o.w = hadd2(a3) + sb[j0 + 3] + s.w * inv;
        Ov[q] = o;
    }
}

// ---------------------------------------------------------------------------
extern "C" void kernel_launch(void* const* d_in, const int* in_sizes, int n_in,
                              void* d_out, int out_size)
{
    const float* x_v   = (const float*)d_in[0];
    const float* x_a   = (const float*)d_in[1];
    const int*   arc   = (const int*)  d_in[2];
    const float* W_vv  = (const float*)d_in[3];
    const float* b_vv  = (const float*)d_in[4];
    const float* W_va  = (const float*)d_in[5];
    const float* W_att = (const float*)d_in[6];
    const float* b_att = (const float*)d_in[7];
    const float* W_aa  = (const float*)d_in[8];
    const float* b_aa  = (const float*)d_in[9];
    const float* W_av  = (const float*)d_in[10];

    float* out_v = (float*)d_out;                     // [NN, 64]
    float* out_a = (float*)d_out + (size_t)NN * 64;   // [NE, 64]

    node_pre_kernel<<<(NN + 255) / 256, 256>>>(x_v, W_av);
    edge_kernel<<<(NE + 255) / 256, 256>>>(x_a, arc, W_va, W_att, b_att,
                                           W_aa, b_aa, out_a);
    node_post_kernel<<<(NN + 255) / 256, 256>>>(x_v, W_vv, b_vv, out_v);
}

// round 8
// speedup vs baseline: 2.4558x; 2.4558x over previous
#include <cuda_runtime.h>
#include <cuda_bf16.h>
#include <cstdint>

#define NN 50000
#define NE 1000000
#define SA 400            // padded smem row stride in BYTES (25x16B, odd multiple of 16 -> conflict-free ldmatrix)
#define KSPLIT 192        // A = [hi | lo | hi],  B = [hi | hi | lo]
#define NSTEP 12          // 192 / 16

// ---------------- device scratch (allocation-free rule) ----------------
__device__ __align__(16) float g_P[NN * 64];     // x_v @ W_av^T
__device__ __align__(16) float g_S[NN * 64];     // unnormalized weighted message sums
__device__ __align__(16) float g_den[NN];        // sum of exp(e) per dst
__device__ __align__(16) __nv_bfloat16 g_Wva_s[64 * KSPLIT];
__device__ __align__(16) __nv_bfloat16 g_Waa_s[64 * KSPLIT];
__device__ __align__(16) __nv_bfloat16 g_Wav_s[64 * KSPLIT];
__device__ __align__(16) __nv_bfloat16 g_Wvv_s[64 * KSPLIT];

// ---------------- helpers ----------------
__device__ __forceinline__ uint32_t smem_u32(const void* p) {
    uint32_t a;
    asm("{ .reg .u64 t; cvta.to.shared.u64 t, %1; cvt.u32.u64 %0, t; }"
        : "=r"(a) : "l"(p));
    return a;
}

__device__ __forceinline__ void ldm_x4(uint32_t* r, uint32_t addr) {
    asm volatile("ldmatrix.sync.aligned.m8n8.x4.shared.b16 {%0,%1,%2,%3}, [%4];"
                 : "=r"(r[0]), "=r"(r[1]), "=r"(r[2]), "=r"(r[3]) : "r"(addr));
}

__device__ __forceinline__ void mma16816(float* c, const uint32_t* a,
                                         uint32_t b0, uint32_t b1) {
    asm volatile(
        "mma.sync.aligned.m16n8k16.row.col.f32.bf16.bf16.f32 "
        "{%0,%1,%2,%3}, {%4,%5,%6,%7}, {%8,%9}, {%0,%1,%2,%3};"
        : "+f"(c[0]), "+f"(c[1]), "+f"(c[2]), "+f"(c[3])
        : "r"(a[0]), "r"(a[1]), "r"(a[2]), "r"(a[3]), "r"(b0), "r"(b1));
}

__device__ __forceinline__ uint32_t pack_bf2(__nv_bfloat16 a, __nv_bfloat16 b) {
    uint32_t ua = __bfloat16_as_ushort(a), ub = __bfloat16_as_ushort(b);
    return ua | (ub << 16);
}

// convert float4 -> hi/lo bf16, store [hi | lo | hi] into padded A row
__device__ __forceinline__ void store_hl(char* Arow, int k, float4 f) {
    __nv_bfloat16 h0 = __float2bfloat16_rn(f.x), h1 = __float2bfloat16_rn(f.y);
    __nv_bfloat16 h2 = __float2bfloat16_rn(f.z), h3 = __float2bfloat16_rn(f.w);
    float l0 = f.x - __bfloat162float(h0), l1 = f.y - __bfloat162float(h1);
    float l2 = f.z - __bfloat162float(h2), l3 = f.w - __bfloat162float(h3);
    uint2 hv = make_uint2(pack_bf2(h0, h1), pack_bf2(h2, h3));
    uint2 lv = make_uint2(
        pack_bf2(__float2bfloat16_rn(l0), __float2bfloat16_rn(l1)),
        pack_bf2(__float2bfloat16_rn(l2), __float2bfloat16_rn(l3)));
    *(uint2*)(Arow + k * 2)       = hv;   // elements [0,64): hi
    *(uint2*)(Arow + 128 + k * 2) = lv;   // elements [64,128): lo
    *(uint2*)(Arow + 256 + k * 2) = hv;   // elements [128,192): hi
}

// core: C[16 x 64] per warp, A[m0..m0+15][K=192], B[64][K=192], both padded SA
__device__ __forceinline__ void gemm_k192(uint32_t aB, uint32_t bB, int m0,
                                          int lane, float c[8][4]) {
#pragma unroll
    for (int i = 0; i < 8; i++)
        c[i][0] = c[i][1] = c[i][2] = c[i][3] = 0.f;
    uint32_t aRow = aB + (uint32_t)(m0 + (lane & 15)) * SA + ((lane >> 4) << 4);
    uint32_t bRow = bB + (uint32_t)(lane & 15) * SA + ((lane >> 4) << 4);
#pragma unroll
    for (int ks = 0; ks < NSTEP; ks++) {
        uint32_t a[4];
        ldm_x4(a, aRow + ks * 32);
#pragma unroll
        for (int np = 0; np < 4; np++) {
            uint32_t b[4];
            ldm_x4(b, bRow + np * 16 * SA + ks * 32);
            mma16816(c[np * 2],     a, b[0], b[2]);
            mma16816(c[np * 2 + 1], a, b[1], b[3]);
        }
    }
}

// ---------------- K-1: weight split prep (runs first, tiny) ----------------
// B layout = [hi | hi | lo] so that A·B = hi·hi + lo·hi + hi·lo.
__global__ void wprep_kernel(const float* __restrict__ Wva,
                             const float* __restrict__ Waa,
                             const float* __restrict__ Wav,
                             const float* __restrict__ Wvv) {
    const float* src[4] = {Wva, Waa, Wav, Wvv};
    __nv_bfloat16* dst[4] = {g_Wva_s, g_Waa_s, g_Wav_s, g_Wvv_s};
    for (int m = 0; m < 4; m++) {
        const float* W = src[m];
        __nv_bfloat16* D = dst[m];
        for (int i = threadIdx.x; i < 4096; i += 256) {
            int j = i >> 6, k = i & 63;
            float f = W[i];
            __nv_bfloat16 h = __float2bfloat16_rn(f);
            __nv_bfloat16 l = __float2bfloat16_rn(f - __bfloat162float(h));
            D[j * KSPLIT + k]       = h;   // [0,64): hi   (pairs with A hi)
            D[j * KSPLIT + 64 + k]  = h;   // [64,128): hi (pairs with A lo)
            D[j * KSPLIT + 128 + k] = l;   // [128,192): lo (pairs with A hi)
        }
    }
}

// ---------------- K0: P = x_v @ W_av^T ; zero S, den ----------------
__global__ void __launch_bounds__(256) node_pre_kernel(const float* __restrict__ x_v)
{
    extern __shared__ char sm[];
    char* A = sm;              // 128*400 = 51200
    char* B = sm + 51200;      // 64*400  = 25600
    int tid = threadIdx.x;
    int nb = blockIdx.x * 128;

    for (int i = tid; i < 64 * 24; i += 256) {
        int r = i / 24, c4 = i % 24;
        ((uint4*)(B + r * SA))[c4] = ((const uint4*)g_Wav_s)[i];
    }
    {
        int r = tid >> 1, ko = (tid & 1) * 32;
        int n = nb + r;
        char* Arow = A + r * SA;
        if (n < NN) {
            const float4* gx = (const float4*)(x_v + (size_t)n * 64 + ko);
#pragma unroll
            for (int i = 0; i < 8; i++) store_hl(Arow, ko + i * 4, gx[i]);
        } else {
            uint2 z = make_uint2(0, 0);
#pragma unroll
            for (int i = 0; i < 8; i++) {
                int k = ko + i * 4;
                *(uint2*)(Arow + k * 2) = z;
                *(uint2*)(Arow + 128 + k * 2) = z;
                *(uint2*)(Arow + 256 + k * 2) = z;
            }
        }
    }
    // zero S rows + den for this block's nodes
    float4 z4 = make_float4(0.f, 0.f, 0.f, 0.f);
    for (int i = tid; i < 2048; i += 256) {
        int n = nb + (i >> 4);
        if (n < NN) ((float4*)(g_S + (size_t)n * 64))[i & 15] = z4;
    }
    if (tid < 128 && nb + tid < NN) g_den[nb + tid] = 0.f;
    __syncthreads();

    int lane = tid & 31, m0 = (tid >> 5) * 16;
    float c[8][4];
    gemm_k192(smem_u32(A), smem_u32(B), m0, lane, c);

    int r0 = m0 + (lane >> 2), r1 = r0 + 8;
    int col0 = (lane & 3) * 2;
    int n0 = nb + r0, n1 = nb + r1;
#pragma unroll
    for (int nt = 0; nt < 8; nt++) {
        int col = nt * 8 + col0;
        if (n0 < NN) *(float2*)(g_P + (size_t)n0 * 64 + col) = make_float2(c[nt][0], c[nt][1]);
        if (n1 < NN) *(float2*)(g_P + (size_t)n1 * 64 + col) = make_float2(c[nt][2], c[nt][3]);
    }
}

// ---------------- K1: edge kernel (tensor-core, 128 edges/block) ----------------
__global__ void __launch_bounds__(256) edge_kernel(
    const float* __restrict__ x_a, const int* __restrict__ arc,
    const float* __restrict__ W_att, const float* __restrict__ b_att,
    const float* __restrict__ b_aa, float* __restrict__ out_a)
{
    extern __shared__ char sm[];
    char*  A    = sm;                       // 51200
    char*  Bva  = sm + 51200;               // 25600
    char*  Baa  = sm + 76800;               // 25600
    float* slog = (float*)(sm + 102400);    // 128 (logit, then exp)
    int*   ssrc = (int*)(sm + 102912);      // 128
    int*   sdst = (int*)(sm + 103424);      // 128
    float* sbias= (float*)(sm + 103936);    // 64

    int tid = threadIdx.x;
    int eb = blockIdx.x * 128;

    // phase 1: weights -> smem; indices; bias; logit init
    for (int i = tid; i < 64 * 24; i += 256) {
        int r = i / 24, c4 = i % 24;
        ((uint4*)(Bva + r * SA))[c4] = ((const uint4*)g_Wva_s)[i];
        ((uint4*)(Baa + r * SA))[c4] = ((const uint4*)g_Waa_s)[i];
    }
    float battv = __ldg(b_att);
    if (tid < 128) {
        int e = eb + tid;
        slog[tid] = (e < NE) ? battv : -1e30f;
        ssrc[tid] = (e < NE) ? __ldg(arc + e) : 0;
    } else {
        int r = tid - 128, e = eb + r;
        sdst[r] = (e < NE) ? __ldg(arc + NE + e) : 0;
        if (tid < 192) sbias[tid - 128] = __ldg(b_aa + (tid - 128));
    }
    __syncthreads();

    // phase 2: A tile load/convert + logit partial dot
    {
        int r = tid >> 1, ko = (tid & 1) * 32;
        int e = eb + r;
        char* Arow = A + r * SA;
        if (e < NE) {
            const float4* gx = (const float4*)(x_a + (size_t)e * 64 + ko);
            const float4* gw = (const float4*)(W_att + ko);
            float part = 0.f;
#pragma unroll
            for (int i = 0; i < 8; i++) {
                float4 f = gx[i];
                float4 wv = __ldg(gw + i);
                part += f.x * wv.x + f.y * wv.y + f.z * wv.z + f.w * wv.w;
                store_hl(Arow, ko + i * 4, f);
            }
            atomicAdd(&slog[r], part);
        } else {
            uint2 z = make_uint2(0, 0);
#pragma unroll
            for (int i = 0; i < 8; i++) {
                int k = ko + i * 4;
                *(uint2*)(Arow + k * 2) = z;
                *(uint2*)(Arow + 128 + k * 2) = z;
                *(uint2*)(Arow + 256 + k * 2) = z;
            }
        }
    }
    __syncthreads();

    // phase 3: w = exp(logit); den atomics
    if (tid < 128) {
        int e = eb + tid;
        float w = __expf(slog[tid]);   // exp(-1e30) = 0 for padding rows
        slog[tid] = w;
        if (e < NE) atomicAdd(&g_den[sdst[tid]], w);
    }
    __syncthreads();

    int lane = tid & 31, m0 = (tid >> 5) * 16;
    uint32_t aB = smem_u32(A);
    float c[8][4];

    // ---- GEMM 1: msg = x_a @ W_va^T ; scatter w*msg into S[dst] ----
    gemm_k192(aB, smem_u32(Bva), m0, lane, c);
    {
        int r0 = m0 + (lane >> 2), r1 = r0 + 8;
        int col0 = (lane & 3) * 2;
        float w0 = slog[r0], w1 = slog[r1];
        float* S0 = g_S + (size_t)sdst[r0] * 64;
        float* S1 = g_S + (size_t)sdst[r1] * 64;
#pragma unroll
        for (int nt = 0; nt < 8; nt++) {
            int col = nt * 8 + col0;
            asm volatile("red.global.add.v2.f32 [%0], {%1,%2};"
                         :: "l"(S0 + col), "f"(c[nt][0] * w0), "f"(c[nt][1] * w0)
                         : "memory");
            asm volatile("red.global.add.v2.f32 [%0], {%1,%2};"
                         :: "l"(S1 + col), "f"(c[nt][2] * w1), "f"(c[nt][3] * w1)
                         : "memory");
        }
    }

    // ---- GEMM 2: out_a = x_a @ W_aa^T + b_aa + P[src] + P[dst] ----
    gemm_k192(aB, smem_u32(Baa), m0, lane, c);
    {
        int r0 = m0 + (lane >> 2), r1 = r0 + 8;
        int col0 = (lane & 3) * 2;
        int e0 = eb + r0, e1 = eb + r1;
        const float* Ps0 = g_P + (size_t)ssrc[r0] * 64;
        const float* Pd0 = g_P + (size_t)sdst[r0] * 64;
        const float* Ps1 = g_P + (size_t)ssrc[r1] * 64;
        const float* Pd1 = g_P + (size_t)sdst[r1] * 64;
#pragma unroll
        for (int nt = 0; nt < 8; nt++) {
            int col = nt * 8 + col0;
            if (e0 < NE) {
                float2 ps = *(const float2*)(Ps0 + col);
                float2 pd = *(const float2*)(Pd0 + col);
                *(float2*)(out_a + (size_t)e0 * 64 + col) =
                    make_float2(c[nt][0] + sbias[col] + ps.x + pd.x,
                                c[nt][1] + sbias[col + 1] + ps.y + pd.y);
            }
            if (e1 < NE) {
                float2 ps = *(const float2*)(Ps1 + col);
                float2 pd = *(const float2*)(Pd1 + col);
                *(float2*)(out_a + (size_t)e1 * 64 + col) =
                    make_float2(c[nt][2] + sbias[col] + ps.x + pd.x,
                                c[nt][3] + sbias[col + 1] + ps.y + pd.y);
            }
        }
    }
}

// ---------------- K2: h_v = x_v @ W_vv^T + b_vv + S/den ----------------
__global__ void __launch_bounds__(256) node_post_kernel(
    const float* __restrict__ x_v, const float* __restrict__ b_vv,
    float* __restrict__ out_v)
{
    extern __shared__ char sm[];
    char*  A  = sm;                  // 51200
    char*  B  = sm + 51200;          // 25600
    float* sb = (float*)(sm + 76800);// 64
    int tid = threadIdx.x;
    int nb = blockIdx.x * 128;

    for (int i = tid; i < 64 * 24; i += 256) {
        int r = i / 24, c4 = i % 24;
        ((uint4*)(B + r * SA))[c4] = ((const uint4*)g_Wvv_s)[i];
    }
    if (tid < 64) sb[tid] = __ldg(b_vv + tid);
    {
        int r = tid >> 1, ko = (tid & 1) * 32;
        int n = nb + r;
        char* Arow = A + r * SA;
        if (n < NN) {
            const float4* gx = (const float4*)(x_v + (size_t)n * 64 + ko);
#pragma unroll
            for (int i = 0; i < 8; i++) store_hl(Arow, ko + i * 4, gx[i]);
        } else {
            uint2 z = make_uint2(0, 0);
#pragma unroll
            for (int i = 0; i < 8; i++) {
                int k = ko + i * 4;
                *(uint2*)(Arow + k * 2) = z;
                *(uint2*)(Arow + 128 + k * 2) = z;
                *(uint2*)(Arow + 256 + k * 2) = z;
            }
        }
    }
    __syncthreads();

    int lane = tid & 31, m0 = (tid >> 5) * 16;
    float c[8][4];
    gemm_k192(smem_u32(A), smem_u32(B), m0, lane, c);

    int r0 = m0 + (lane >> 2), r1 = r0 + 8;
    int col0 = (lane & 3) * 2;
    int n0 = nb + r0, n1 = nb + r1;
    float inv0 = 0.f, inv1 = 0.f;
    if (n0 < NN) { float d = g_den[n0]; inv0 = (d > 0.f) ? 1.f / d : 0.f; }
    if (n1 < NN) { float d = g_den[n1]; inv1 = (d > 0.f) ? 1.f / d : 0.f; }
#pragma unroll
    for (int nt = 0; nt < 8; nt++) {
        int col = nt * 8 + col0;
        if (n0 < NN) {
            float2 s = *(const float2*)(g_S + (size_t)n0 * 64 + col);
            *(float2*)(out_v + (size_t)n0 * 64 + col) =
                make_float2(c[nt][0] + sb[col] + s.x * inv0,
                            c[nt][1] + sb[col + 1] + s.y * inv0);
        }
        if (n1 < NN) {
            float2 s = *(const float2*)(g_S + (size_t)n1 * 64 + col);
            *(float2*)(out_v + (size_t)n1 * 64 + col) =
                make_float2(c[nt][2] + sb[col] + s.x * inv1,
                            c[nt][3] + sb[col + 1] + s.y * inv1);
        }
    }
}

// ---------------------------------------------------------------------------
extern "C" void kernel_launch(void* const* d_in, const int* in_sizes, int n_in,
                              void* d_out, int out_size)
{
    const float* x_v   = (const float*)d_in[0];
    const float* x_a   = (const float*)d_in[1];
    const int*   arc   = (const int*)  d_in[2];
    const float* W_vv  = (const float*)d_in[3];
    const float* b_vv  = (const float*)d_in[4];
    const float* W_va  = (const float*)d_in[5];
    const float* W_att = (const float*)d_in[6];
    const float* b_att = (const float*)d_in[7];
    const float* W_aa  = (const float*)d_in[8];
    const float* b_aa  = (const float*)d_in[9];
    const float* W_av  = (const float*)d_in[10];

    float* out_v = (float*)d_out;                     // [NN, 64]
    float* out_a = (float*)d_out + (size_t)NN * 64;   // [NE, 64]

    const int EDGE_SMEM = 104448;
    const int NODE_SMEM = 77312;
    cudaFuncSetAttribute(edge_kernel, cudaFuncAttributeMaxDynamicSharedMemorySize, EDGE_SMEM);
    cudaFuncSetAttribute(node_pre_kernel, cudaFuncAttributeMaxDynamicSharedMemorySize, NODE_SMEM);
    cudaFuncSetAttribute(node_post_kernel, cudaFuncAttributeMaxDynamicSharedMemorySize, NODE_SMEM);

    wprep_kernel<<<1, 256>>>(W_va, W_aa, W_av, W_vv);
    node_pre_kernel<<<(NN + 127) / 128, 256, NODE_SMEM>>>(x_v);
    edge_kernel<<<(NE + 127) / 128, 256, EDGE_SMEM>>>(x_a, arc, W_att, b_att,
                                                      b_aa, out_a);
    node_post_kernel<<<(NN + 127) / 128, 256, NODE_SMEM>>>(x_v, b_vv, out_v);
}